// round 16
// baseline (speedup 1.0000x reference)
#include <cuda_runtime.h>
#include <math.h>
#include <stdint.h>

#define N_AG 1024
#define T_STEPS 32
#define KC 3136            // 49 live cells * 64 hidden

// ---------------- device scratch (no allocations allowed) ----------------
__device__ float g_Hc[N_AG * KC];        // compact social tensor rows (active agents only)
__device__ float g_Z[N_AG * 384];        // [r(64) | e(256) | h(64)]
__device__ float g_E[4 * N_AG * 256];    // split-K raw partials
__device__ float g_h[N_AG * 64];
__device__ float g_c[N_AG * 64];
__device__ float g_hA[N_AG * 64];        // compacted active-agent h (contiguous)
__device__ float g_Wsc[KC * 256];        // W_soc permuted to compact cell order
__device__ float g_Wcat[384 * 256];      // [W_ih(320x256) ; W_hh(64x256)]
__device__ float g_bc[256];              // b_ih + b_hh
__device__ float g_cx[N_AG], g_cy[N_AG]; // compacted active-agent coords
__device__ short g_jid[N_AG];            // compact pos -> agent id
__device__ short g_pos[N_AG];            // agent id -> compact pos (or -1)
__device__ int   g_nact;

__device__ __forceinline__ float sigf(float x) { return 1.f / (1.f + expf(-x)); }

// ---------------- one-time init ----------------
__global__ void k_init(const float* __restrict__ h0, const float* __restrict__ c0,
                       const float* __restrict__ Wih, const float* __restrict__ bih,
                       const float* __restrict__ Whh, const float* __restrict__ bhh)
{
    int gid = blockIdx.x * 256 + threadIdx.x;   // grid 384 -> 98304 = 384*256
    int k = gid >> 8, g = gid & 255;
    g_Wcat[gid] = (k < 320) ? Wih[gid] : Whh[(k - 320) * 256 + g];
    if (gid < N_AG * 64) { g_h[gid] = h0[gid]; g_c[gid] = c0[gid]; }
    if (gid < 256) g_bc[gid] = bih[gid] + bhh[gid];
}

// permute W_soc rows into compact 49-cell order (once)
__global__ void k_initw(const float* __restrict__ Wsoc)
{
    int row = blockIdx.x;                       // 0..3135
    int cc = row >> 6, h = row & 63;
    int orow = ((cc / 7 + 1) * 8 + (cc % 7 + 1)) * 64 + h;
    g_Wsc[row * 256 + threadIdx.x] = Wsoc[orow * 256 + threadIdx.x];
}

// ---------------- per-step: deterministic compaction of active agents ----------------
__global__ void k_compact(const float* __restrict__ X, const int* __restrict__ pm,
                          const int* __restrict__ Tp, int t)
{
    if (t > *Tp) return;
    int j = threadIdx.x;                        // 1024 threads, 1 CTA
    int m = pm[t * N_AG + j];
    unsigned b = __ballot_sync(0xFFFFFFFFu, m);
    int lane = j & 31, w = j >> 5;
    __shared__ int wcnt[32], woff[32];
    if (lane == 0) wcnt[w] = __popc(b);
    __syncthreads();
    if (j < 32) {
        int v = wcnt[j], incl = v;
        #pragma unroll
        for (int o = 1; o < 32; o <<= 1) {
            int u = __shfl_up_sync(0xFFFFFFFFu, incl, o);
            if (j >= o) incl += u;
        }
        woff[j] = incl - v;
        if (j == 31) g_nact = incl;
    }
    __syncthreads();
    if (m) {
        int pos = woff[w] + __popc(b & ((1u << lane) - 1));
        g_cx[pos] = X[(t * N_AG + j) * 4 + 2];
        g_cy[pos] = X[(t * N_AG + j) * 4 + 3];
        g_jid[pos] = (short)j;
        g_pos[j] = (short)pos;
    } else {
        g_pos[j] = -1;
    }
}

// ---------------- per-step: gather active h rows into contiguous g_hA ----------------
__global__ void k_gather(const int* __restrict__ Tp, int t)
{
    if (t > *Tp) return;
    int gid = blockIdx.x * 256 + threadIdx.x;   // grid 256 -> 65536 = 1024*64
    int pos = gid >> 6, lane = gid & 63;
    if (pos < g_nact)
        g_hA[gid] = g_h[(int)g_jid[pos] * 64 + lane];
}

// ---------------- per-step: social pool (compact rows) + fused input embedding ----------------
// one CTA (128 thr) per agent i; masked i exits after Z staging.
__global__ void __launch_bounds__(128) k_pool(const float* __restrict__ X,
                                              const float* __restrict__ Wemb,
                                              const float* __restrict__ bemb,
                                              const int* __restrict__ Tp, int t)
{
    if (t > *Tp) return;
    const int i = blockIdx.x, tid = threadIdx.x;

    // fused "prep": r = relu(coords@W_emb+b) -> Z[:,0:64]; copy h -> Z[:,320:384]
    if (tid < 64) {
        float x2 = X[(t * N_AG + i) * 4 + 2];
        float x3 = X[(t * N_AG + i) * 4 + 3];
        g_Z[i * 384 + tid] = fmaxf(bemb[tid] + x2 * Wemb[tid] + x3 * Wemb[64 + tid], 0.f);
    } else {
        int k = tid - 64;
        g_Z[i * 384 + 320 + k] = g_h[i * 64 + k];
    }

    const int posi = g_pos[i];
    if (posi < 0) return;                       // masked agent: no H row needed

    __shared__ float Hs[2][KC];
    __shared__ short cellS[N_AG];
    for (int idx = tid; idx < 2 * KC; idx += 128) ((float*)Hs)[idx] = 0.f;

    const int na = g_nact;
    const float cx = X[(t * N_AG + i) * 4 + 2];
    const float cy = X[(t * N_AG + i) * 4 + 3];
    for (int j = tid; j < na; j += 128) {
        float gx = truncf(g_cx[j] - cx);
        float gy = truncf(g_cy[j] - cy);
        int c = -1;
        if (j != posi && fabsf(gx) <= 3.f && fabsf(gy) <= 3.f)
            c = ((int)gx + 3) * 7 + ((int)gy + 3);
        cellS[j] = (short)c;
    }
    __syncthreads();

    const int grp = tid >> 6, lane = tid & 63;
    const int half = (na + 1) >> 1;
    const int j0 = grp ? half : 0, j1 = grp ? na : half;
    float* hsb = &Hs[grp][lane];
    const float* hp = g_hA + lane;

    int j = j0;
    for (; j + 3 < j1; j += 4) {
        int c0 = cellS[j], c1 = cellS[j + 1], c2 = cellS[j + 2], c3 = cellS[j + 3];
        float h0 = hp[j * 64];
        float h1 = hp[(j + 1) * 64];
        float h2 = hp[(j + 2) * 64];
        float h3 = hp[(j + 3) * 64];
        if (c0 >= 0) hsb[c0 * 64] += h0;
        if (c1 >= 0) hsb[c1 * 64] += h1;
        if (c2 >= 0) hsb[c2 * 64] += h2;
        if (c3 >= 0) hsb[c3 * 64] += h3;
    }
    for (; j < j1; ++j) {
        int c = cellS[j];
        if (c >= 0) hsb[c * 64] += hp[j * 64];
    }
    __syncthreads();

    float* Ho = g_Hc + (size_t)posi * KC;       // compact row
    for (int idx = tid; idx < KC; idx += 128)
        Ho[idx] = Hs[0][idx] + Hs[1][idx];
}

// ================= tensor-core GEMM (3xTF32 mma.sync), split-K =================
// MODE 0: g_Hc(nact x KC) @ g_Wsc(KCx256), 98 BK=32 tiles, split-K=4 -> g_E[0..3]
//         (M-tiles beyond nact exit immediately)
// MODE 1: g_Z(1024x384) @ g_Wcat(384x256), 12 tiles, split-K=2 -> g_E[0..1]

__device__ __forceinline__ void cpa16(uint32_t s, const void* g) {
    asm volatile("cp.async.cg.shared.global [%0], [%1], 16;" :: "r"(s), "l"(g));
}

__device__ __forceinline__ void split_tf32(float x, uint32_t& hi, uint32_t& lo) {
    asm("cvt.rna.tf32.f32 %0, %1;" : "=r"(hi) : "f"(x));
    float r = x - __uint_as_float(hi);
    asm("cvt.rna.tf32.f32 %0, %1;" : "=r"(lo) : "f"(r));
}

__device__ __forceinline__ void mma_tf32(float c[4], const uint32_t a[4], const uint32_t b[2]) {
    asm volatile(
        "mma.sync.aligned.m16n8k8.row.col.f32.tf32.tf32.f32 "
        "{%0,%1,%2,%3}, {%4,%5,%6,%7}, {%8,%9}, {%0,%1,%2,%3};"
        : "+f"(c[0]), "+f"(c[1]), "+f"(c[2]), "+f"(c[3])
        : "r"(a[0]), "r"(a[1]), "r"(a[2]), "r"(a[3]), "r"(b[0]), "r"(b[1]));
}

#define LDA_S 36
#define LDB_S 72

template <int LDA>
__device__ __forceinline__ void stage_tile(const float* __restrict__ Ag,
                                           const float* __restrict__ Bg,
                                           float* Asb, float* Bsb,
                                           int bm, int bn, int k0, int tid)
{
    uint32_t sa = (uint32_t)__cvta_generic_to_shared(Asb);
    uint32_t sb = (uint32_t)__cvta_generic_to_shared(Bsb);
    #pragma unroll
    for (int q = 0; q < 4; ++q) {               // A: 64x32 floats
        int idx = tid + 128 * q;
        int m = idx >> 3, kq = (idx & 7) << 2;
        cpa16(sa + (uint32_t)(m * LDA_S + kq) * 4,
              Ag + (size_t)(bm + m) * LDA + k0 + kq);
    }
    #pragma unroll
    for (int q = 0; q < 4; ++q) {               // B: 32x64 floats
        int idx = tid + 128 * q;
        int k = idx >> 4, nq = (idx & 15) << 2;
        cpa16(sb + (uint32_t)(k * LDB_S + nq) * 4,
              Bg + (size_t)(k0 + k) * 256 + bn + nq);
    }
    asm volatile("cp.async.commit_group;");
}

template <int MODE>
__global__ void __launch_bounds__(128) k_mma(const int* __restrict__ Tp, int t)
{
    if (t > *Tp) return;
    constexpr int LDA = (MODE == 0) ? KC : 384;
    constexpr int NTT = (MODE == 0) ? 98 : 12;
    constexpr int NS  = (MODE == 0) ? 4 : 2;

    const int bm = blockIdx.x * 64;
    if (MODE == 0 && bm >= g_nact) return;      // compact-M: skip dead tiles

    const float* Ag = (MODE == 0) ? g_Hc : g_Z;
    const float* Bg = (MODE == 0) ? g_Wsc : g_Wcat;
    const int z = blockIdx.z;
    float* Cg = g_E + (size_t)z * (N_AG * 256);
    const int tbeg = z * NTT / NS, tend = (z + 1) * NTT / NS;

    __shared__ float As[2][64 * LDA_S];
    __shared__ float Bs[2][32 * LDB_S];

    const int tid = threadIdx.x;
    const int lane = tid & 31, w = tid >> 5;
    const int group = lane >> 2, tg = lane & 3;
    const int wm = (w & 1) * 32, wn = (w >> 1) * 32;
    const int bn = blockIdx.y * 64;

    float acc[2][4][4];
    #pragma unroll
    for (int i = 0; i < 2; ++i)
        #pragma unroll
        for (int j = 0; j < 4; ++j)
            #pragma unroll
            for (int v = 0; v < 4; ++v) acc[i][j][v] = 0.f;

    stage_tile<LDA>(Ag, Bg, As[0], Bs[0], bm, bn, tbeg * 32, tid);

    for (int it = tbeg; it < tend; ++it) {
        const int cur = (it - tbeg) & 1;
        if (it + 1 < tend) {
            stage_tile<LDA>(Ag, Bg, As[cur ^ 1], Bs[cur ^ 1], bm, bn, (it + 1) * 32, tid);
            asm volatile("cp.async.wait_group 1;");
        } else {
            asm volatile("cp.async.wait_group 0;");
        }
        __syncthreads();

        const float* Ab = As[cur];
        const float* Bb = Bs[cur];
        #pragma unroll
        for (int ka = 0; ka < 4; ++ka) {
            const int kk = ka * 8 + tg;
            uint32_t ahi[2][4], alo[2][4];
            #pragma unroll
            for (int im = 0; im < 2; ++im) {
                int r0 = wm + im * 16 + group;
                split_tf32(Ab[r0 * LDA_S + kk],           ahi[im][0], alo[im][0]);
                split_tf32(Ab[(r0 + 8) * LDA_S + kk],     ahi[im][1], alo[im][1]);
                split_tf32(Ab[r0 * LDA_S + kk + 4],       ahi[im][2], alo[im][2]);
                split_tf32(Ab[(r0 + 8) * LDA_S + kk + 4], ahi[im][3], alo[im][3]);
            }
            uint32_t bhi[4][2], blo[4][2];
            #pragma unroll
            for (int jn = 0; jn < 4; ++jn) {
                int nn = wn + jn * 8 + group;
                split_tf32(Bb[kk * LDB_S + nn],       bhi[jn][0], blo[jn][0]);
                split_tf32(Bb[(kk + 4) * LDB_S + nn], bhi[jn][1], blo[jn][1]);
            }
            #pragma unroll
            for (int im = 0; im < 2; ++im)
                #pragma unroll
                for (int jn = 0; jn < 4; ++jn) {
                    mma_tf32(acc[im][jn], ahi[im], bhi[jn]);
                    mma_tf32(acc[im][jn], ahi[im], blo[jn]);
                    mma_tf32(acc[im][jn], alo[im], bhi[jn]);
                }
        }
        __syncthreads();
    }

    #pragma unroll
    for (int im = 0; im < 2; ++im) {
        const int row = bm + wm + im * 16 + group;
        #pragma unroll
        for (int jn = 0; jn < 4; ++jn) {
            const int col = bn + wn + jn * 8 + tg * 2;
            *(float2*)&Cg[(size_t)row * 256 + col] = make_float2(acc[im][jn][0], acc[im][jn][1]);
            *(float2*)&Cg[(size_t)(row + 8) * 256 + col] = make_float2(acc[im][jn][2], acc[im][jn][3]);
        }
    }
}

// ---------------- combine: e = relu(sum partials[pos] + b_soc) scattered to Z ----------------
__global__ void k_comb(const float* __restrict__ bsoc, const int* __restrict__ Tp, int t)
{
    if (t > *Tp) return;
    int gid = blockIdx.x * 256 + threadIdx.x;   // grid 1024 -> 262144
    int n = gid >> 8, c = gid & 255;
    int p = g_pos[n];
    float s = bsoc[c];
    if (p >= 0) {
        size_t off = (size_t)p * 256 + c;
        s += g_E[off] + g_E[N_AG * 256 + off]
           + g_E[2 * N_AG * 256 + off] + g_E[3 * N_AG * 256 + off];
    }
    g_Z[n * 384 + 64 + c] = fmaxf(s, 0.f);
}

// ---------------- per-step: LSTM cell (sums 2 gates partials) + output head ----------------
__global__ void k_lstm(const float* __restrict__ Wout, const float* __restrict__ bout,
                       const int* __restrict__ pm, const float* __restrict__ Y,
                       float* __restrict__ out, const int* __restrict__ Tp, int t)
{
    const int n = blockIdx.x * 8 + (threadIdx.x >> 5);
    const int lane = threadIdx.x & 31;

    if (t > *Tp) {
        if (lane < 2) out[(size_t)(t * N_AG + n) * 2 + lane] = 0.f;
        return;
    }

    const float* g0 = g_E + (size_t)n * 256;
    const float* g1 = g_E + N_AG * 256 + (size_t)n * 256;
    #define GATE(o) (g0[o] + g1[o] + g_bc[o])
    float i0 = GATE(lane),        i1 = GATE(32 + lane);
    float f0 = GATE(64 + lane),   f1 = GATE(96 + lane);
    float gg0 = GATE(128 + lane), gg1 = GATE(160 + lane);
    float o0 = GATE(192 + lane),  o1 = GATE(224 + lane);
    #undef GATE

    float c0 = g_c[n * 64 + lane], c1 = g_c[n * 64 + 32 + lane];
    float cn0 = sigf(f0) * c0 + sigf(i0) * tanhf(gg0);
    float cn1 = sigf(f1) * c1 + sigf(i1) * tanhf(gg1);
    float hn0 = sigf(o0) * tanhf(cn0);
    float hn1 = sigf(o1) * tanhf(cn1);

    g_c[n * 64 + lane] = cn0; g_c[n * 64 + 32 + lane] = cn1;
    g_h[n * 64 + lane] = hn0; g_h[n * 64 + 32 + lane] = hn1;

    float s0 = hn0 * Wout[lane * 2 + 0] + hn1 * Wout[(lane + 32) * 2 + 0];
    float s1 = hn0 * Wout[lane * 2 + 1] + hn1 * Wout[(lane + 32) * 2 + 1];
    #pragma unroll
    for (int off = 16; off; off >>= 1) {
        s0 += __shfl_down_sync(0xFFFFFFFFu, s0, off);
        s1 += __shfl_down_sync(0xFFFFFFFFu, s1, off);
    }

    if (lane == 0) {
        const int m  = pm[t * N_AG + n];
        const int m3 = (t < 3) ? 1 : pm[(t - 3) * N_AG + n];
        float v0 = s0 + bout[0];
        float v1 = s1 + bout[1];
        if (!m) { v0 = 0.f; v1 = 0.f; }
        if (t > 3 && m && !m3) {
            v0 = Y[(size_t)(t * N_AG + n) * 2 + 0];
            v1 = Y[(size_t)(t * N_AG + n) * 2 + 1];
        }
        out[(size_t)(t * N_AG + n) * 2 + 0] = v0;
        out[(size_t)(t * N_AG + n) * 2 + 1] = v1;
    }
}

// ---------------- host launcher (graph-capturable: kernels only) ----------------
extern "C" void kernel_launch(void* const* d_in, const int* in_sizes, int n_in,
                              void* d_out, int out_size)
{
    const float* X    = (const float*)d_in[0];
    const int*   pm   = (const int*)  d_in[1];
    const float* h0   = (const float*)d_in[2];
    const float* c0   = (const float*)d_in[3];
    const float* Y    = (const float*)d_in[4];
    // d_in[5] = T_obs (unused)
    const int*   Tp   = (const int*)  d_in[6];
    const float* Wemb = (const float*)d_in[7];
    const float* bemb = (const float*)d_in[8];
    const float* Wsoc = (const float*)d_in[9];
    const float* bsoc = (const float*)d_in[10];
    const float* Wih  = (const float*)d_in[11];
    const float* bih  = (const float*)d_in[12];
    const float* Whh  = (const float*)d_in[13];
    const float* bhh  = (const float*)d_in[14];
    const float* Wout = (const float*)d_in[15];
    const float* bout = (const float*)d_in[16];
    float* out = (float*)d_out;

    k_init<<<384, 256>>>(h0, c0, Wih, bih, Whh, bhh);
    k_initw<<<KC, 256>>>(Wsoc);

    for (int t = 0; t < T_STEPS; ++t) {
        k_compact<<<1, 1024>>>(X, pm, Tp, t);
        k_gather<<<256, 256>>>(Tp, t);
        k_pool<<<N_AG, 128>>>(X, Wemb, bemb, Tp, t);
        k_mma<0><<<dim3(16, 4, 4), 128>>>(Tp, t);   // social GEMM (compact M), split-K=4
        k_comb<<<1024, 256>>>(bsoc, Tp, t);
        k_mma<1><<<dim3(16, 4, 2), 128>>>(Tp, t);   // gates GEMM, split-K=2
        k_lstm<<<128, 256>>>(Wout, bout, pm, Y, out, Tp, t);
    }
}

// round 17
// speedup vs baseline: 1.0630x; 1.0630x over previous
#include <cuda_runtime.h>
#include <math.h>
#include <stdint.h>

#define N_AG 1024
#define T_STEPS 32
#define KC 3136            // 49 live cells * 64 hidden

// ---------------- device scratch (no allocations allowed) ----------------
__device__ float g_Hc[N_AG * KC];        // compact social tensor rows (active agents only)
__device__ float g_Z[N_AG * 384];        // [r(64) | e(256) | h(64)]
__device__ float g_E[4 * N_AG * 256];    // split-K raw partials
__device__ float g_h[N_AG * 64];
__device__ float g_c[N_AG * 64];
__device__ float g_Wsc[KC * 256];        // W_soc permuted to compact cell order
__device__ float g_Wcat[384 * 256];      // [W_ih(320x256) ; W_hh(64x256)]
__device__ float g_bc[256];              // b_ih + b_hh
// per-timestep compaction tables (precomputed once; mask/coords don't depend on state)
__device__ float g_cxT[T_STEPS][N_AG], g_cyT[T_STEPS][N_AG];
__device__ short g_jidT[T_STEPS][N_AG]; // compact pos -> agent id
__device__ short g_posT[T_STEPS][N_AG]; // agent id -> compact pos (or -1)
__device__ int   g_nactT[T_STEPS];

__device__ __forceinline__ float sigf(float x) { return 1.f / (1.f + expf(-x)); }

// ---------------- one-time init ----------------
__global__ void k_init(const float* __restrict__ h0, const float* __restrict__ c0,
                       const float* __restrict__ Wih, const float* __restrict__ bih,
                       const float* __restrict__ Whh, const float* __restrict__ bhh)
{
    int gid = blockIdx.x * 256 + threadIdx.x;   // grid 384 -> 98304 = 384*256
    int k = gid >> 8, g = gid & 255;
    g_Wcat[gid] = (k < 320) ? Wih[gid] : Whh[(k - 320) * 256 + g];
    if (gid < N_AG * 64) { g_h[gid] = h0[gid]; g_c[gid] = c0[gid]; }
    if (gid < 256) g_bc[gid] = bih[gid] + bhh[gid];
}

// permute W_soc rows into compact 49-cell order (once)
__global__ void k_initw(const float* __restrict__ Wsoc)
{
    int row = blockIdx.x;                       // 0..3135
    int cc = row >> 6, h = row & 63;
    int orow = ((cc / 7 + 1) * 8 + (cc % 7 + 1)) * 64 + h;
    g_Wsc[row * 256 + threadIdx.x] = Wsoc[orow * 256 + threadIdx.x];
}

// ---------------- one-time: compaction tables for ALL timesteps ----------------
__global__ void k_compact_all(const float* __restrict__ X, const int* __restrict__ pm)
{
    const int t = blockIdx.x;                   // one CTA (1024 thr) per timestep
    int j = threadIdx.x;
    int m = pm[t * N_AG + j];
    unsigned b = __ballot_sync(0xFFFFFFFFu, m);
    int lane = j & 31, w = j >> 5;
    __shared__ int wcnt[32], woff[32];
    if (lane == 0) wcnt[w] = __popc(b);
    __syncthreads();
    if (j < 32) {
        int v = wcnt[j], incl = v;
        #pragma unroll
        for (int o = 1; o < 32; o <<= 1) {
            int u = __shfl_up_sync(0xFFFFFFFFu, incl, o);
            if (j >= o) incl += u;
        }
        woff[j] = incl - v;
        if (j == 31) g_nactT[t] = incl;
    }
    __syncthreads();
    if (m) {
        int pos = woff[w] + __popc(b & ((1u << lane) - 1));
        g_cxT[t][pos] = X[(t * N_AG + j) * 4 + 2];
        g_cyT[t][pos] = X[(t * N_AG + j) * 4 + 3];
        g_jidT[t][pos] = (short)j;
        g_posT[t][j] = (short)pos;
    } else {
        g_posT[t][j] = -1;
    }
}

// ---------------- per-step: social pool (compact rows) + fused input embedding ----------------
// one CTA (128 thr) per agent i; masked i exits after Z staging.
__global__ void __launch_bounds__(128) k_pool(const float* __restrict__ X,
                                              const float* __restrict__ Wemb,
                                              const float* __restrict__ bemb,
                                              const int* __restrict__ Tp, int t)
{
    if (t > *Tp) return;
    const int i = blockIdx.x, tid = threadIdx.x;

    // fused "prep": r = relu(coords@W_emb+b) -> Z[:,0:64]; copy h -> Z[:,320:384]
    if (tid < 64) {
        float x2 = X[(t * N_AG + i) * 4 + 2];
        float x3 = X[(t * N_AG + i) * 4 + 3];
        g_Z[i * 384 + tid] = fmaxf(bemb[tid] + x2 * Wemb[tid] + x3 * Wemb[64 + tid], 0.f);
    } else {
        int k = tid - 64;
        g_Z[i * 384 + 320 + k] = g_h[i * 64 + k];
    }

    const int posi = g_posT[t][i];
    if (posi < 0) return;                       // masked agent: no H row needed

    __shared__ float Hs[2][KC];
    __shared__ short cellS[N_AG], jidS[N_AG];
    for (int idx = tid; idx < 2 * KC; idx += 128) ((float*)Hs)[idx] = 0.f;

    const int na = g_nactT[t];
    const float cx = g_cxT[t][posi];
    const float cy = g_cyT[t][posi];
    for (int j = tid; j < na; j += 128) {
        float gx = truncf(g_cxT[t][j] - cx);
        float gy = truncf(g_cyT[t][j] - cy);
        int c = -1;
        if (j != posi && fabsf(gx) <= 3.f && fabsf(gy) <= 3.f)
            c = ((int)gx + 3) * 7 + ((int)gy + 3);
        cellS[j] = (short)c;
        jidS[j] = g_jidT[t][j];
    }
    __syncthreads();

    const int grp = tid >> 6, lane = tid & 63;
    const int half = (na + 1) >> 1;
    const int j0 = grp ? half : 0, j1 = grp ? na : half;
    float* hsb = &Hs[grp][lane];
    const float* hp = g_h + lane;

    int j = j0;
    for (; j + 3 < j1; j += 4) {
        int c0 = cellS[j], c1 = cellS[j + 1], c2 = cellS[j + 2], c3 = cellS[j + 3];
        float h0 = hp[(int)jidS[j] * 64];
        float h1 = hp[(int)jidS[j + 1] * 64];
        float h2 = hp[(int)jidS[j + 2] * 64];
        float h3 = hp[(int)jidS[j + 3] * 64];
        if (c0 >= 0) hsb[c0 * 64] += h0;
        if (c1 >= 0) hsb[c1 * 64] += h1;
        if (c2 >= 0) hsb[c2 * 64] += h2;
        if (c3 >= 0) hsb[c3 * 64] += h3;
    }
    for (; j < j1; ++j) {
        int c = cellS[j];
        if (c >= 0) hsb[c * 64] += hp[(int)jidS[j] * 64];
    }
    __syncthreads();

    float* Ho = g_Hc + (size_t)posi * KC;       // compact row
    for (int idx = tid; idx < KC; idx += 128)
        Ho[idx] = Hs[0][idx] + Hs[1][idx];
}

// ================= tensor-core GEMM (3xTF32 mma.sync), split-K =================
// MODE 0: g_Hc(nact x KC) @ g_Wsc(KCx256), 98 BK=32 tiles, split-K=4 -> g_E[0..3]
//         (M-tiles beyond nact exit immediately)
// MODE 1: g_Z(1024x384) @ g_Wcat(384x256), 12 tiles, split-K=2 -> g_E[0..1]

__device__ __forceinline__ void cpa16(uint32_t s, const void* g) {
    asm volatile("cp.async.cg.shared.global [%0], [%1], 16;" :: "r"(s), "l"(g));
}

__device__ __forceinline__ void split_tf32(float x, uint32_t& hi, uint32_t& lo) {
    asm("cvt.rna.tf32.f32 %0, %1;" : "=r"(hi) : "f"(x));
    float r = x - __uint_as_float(hi);
    asm("cvt.rna.tf32.f32 %0, %1;" : "=r"(lo) : "f"(r));
}

__device__ __forceinline__ void mma_tf32(float c[4], const uint32_t a[4], const uint32_t b[2]) {
    asm volatile(
        "mma.sync.aligned.m16n8k8.row.col.f32.tf32.tf32.f32 "
        "{%0,%1,%2,%3}, {%4,%5,%6,%7}, {%8,%9}, {%0,%1,%2,%3};"
        : "+f"(c[0]), "+f"(c[1]), "+f"(c[2]), "+f"(c[3])
        : "r"(a[0]), "r"(a[1]), "r"(a[2]), "r"(a[3]), "r"(b[0]), "r"(b[1]));
}

#define LDA_S 36
#define LDB_S 72

template <int LDA>
__device__ __forceinline__ void stage_tile(const float* __restrict__ Ag,
                                           const float* __restrict__ Bg,
                                           float* Asb, float* Bsb,
                                           int bm, int bn, int k0, int tid)
{
    uint32_t sa = (uint32_t)__cvta_generic_to_shared(Asb);
    uint32_t sb = (uint32_t)__cvta_generic_to_shared(Bsb);
    #pragma unroll
    for (int q = 0; q < 4; ++q) {               // A: 64x32 floats
        int idx = tid + 128 * q;
        int m = idx >> 3, kq = (idx & 7) << 2;
        cpa16(sa + (uint32_t)(m * LDA_S + kq) * 4,
              Ag + (size_t)(bm + m) * LDA + k0 + kq);
    }
    #pragma unroll
    for (int q = 0; q < 4; ++q) {               // B: 32x64 floats
        int idx = tid + 128 * q;
        int k = idx >> 4, nq = (idx & 15) << 2;
        cpa16(sb + (uint32_t)(k * LDB_S + nq) * 4,
              Bg + (size_t)(k0 + k) * 256 + bn + nq);
    }
    asm volatile("cp.async.commit_group;");
}

template <int MODE>
__global__ void __launch_bounds__(128) k_mma(const int* __restrict__ Tp, int t)
{
    if (t > *Tp) return;
    constexpr int LDA = (MODE == 0) ? KC : 384;
    constexpr int NTT = (MODE == 0) ? 98 : 12;
    constexpr int NS  = (MODE == 0) ? 4 : 2;

    const int bm = blockIdx.x * 64;
    if (MODE == 0 && bm >= g_nactT[t]) return;  // compact-M: skip dead tiles

    const float* Ag = (MODE == 0) ? g_Hc : g_Z;
    const float* Bg = (MODE == 0) ? g_Wsc : g_Wcat;
    const int z = blockIdx.z;
    float* Cg = g_E + (size_t)z * (N_AG * 256);
    const int tbeg = z * NTT / NS, tend = (z + 1) * NTT / NS;

    __shared__ float As[2][64 * LDA_S];
    __shared__ float Bs[2][32 * LDB_S];

    const int tid = threadIdx.x;
    const int lane = tid & 31, w = tid >> 5;
    const int group = lane >> 2, tg = lane & 3;
    const int wm = (w & 1) * 32, wn = (w >> 1) * 32;
    const int bn = blockIdx.y * 64;

    float acc[2][4][4];
    #pragma unroll
    for (int i = 0; i < 2; ++i)
        #pragma unroll
        for (int j = 0; j < 4; ++j)
            #pragma unroll
            for (int v = 0; v < 4; ++v) acc[i][j][v] = 0.f;

    stage_tile<LDA>(Ag, Bg, As[0], Bs[0], bm, bn, tbeg * 32, tid);

    for (int it = tbeg; it < tend; ++it) {
        const int cur = (it - tbeg) & 1;
        if (it + 1 < tend) {
            stage_tile<LDA>(Ag, Bg, As[cur ^ 1], Bs[cur ^ 1], bm, bn, (it + 1) * 32, tid);
            asm volatile("cp.async.wait_group 1;");
        } else {
            asm volatile("cp.async.wait_group 0;");
        }
        __syncthreads();

        const float* Ab = As[cur];
        const float* Bb = Bs[cur];
        #pragma unroll
        for (int ka = 0; ka < 4; ++ka) {
            const int kk = ka * 8 + tg;
            uint32_t ahi[2][4], alo[2][4];
            #pragma unroll
            for (int im = 0; im < 2; ++im) {
                int r0 = wm + im * 16 + group;
                split_tf32(Ab[r0 * LDA_S + kk],           ahi[im][0], alo[im][0]);
                split_tf32(Ab[(r0 + 8) * LDA_S + kk],     ahi[im][1], alo[im][1]);
                split_tf32(Ab[r0 * LDA_S + kk + 4],       ahi[im][2], alo[im][2]);
                split_tf32(Ab[(r0 + 8) * LDA_S + kk + 4], ahi[im][3], alo[im][3]);
            }
            uint32_t bhi[4][2], blo[4][2];
            #pragma unroll
            for (int jn = 0; jn < 4; ++jn) {
                int nn = wn + jn * 8 + group;
                split_tf32(Bb[kk * LDB_S + nn],       bhi[jn][0], blo[jn][0]);
                split_tf32(Bb[(kk + 4) * LDB_S + nn], bhi[jn][1], blo[jn][1]);
            }
            #pragma unroll
            for (int im = 0; im < 2; ++im)
                #pragma unroll
                for (int jn = 0; jn < 4; ++jn) {
                    mma_tf32(acc[im][jn], ahi[im], bhi[jn]);
                    mma_tf32(acc[im][jn], ahi[im], blo[jn]);
                    mma_tf32(acc[im][jn], alo[im], bhi[jn]);
                }
        }
        __syncthreads();
    }

    #pragma unroll
    for (int im = 0; im < 2; ++im) {
        const int row = bm + wm + im * 16 + group;
        #pragma unroll
        for (int jn = 0; jn < 4; ++jn) {
            const int col = bn + wn + jn * 8 + tg * 2;
            *(float2*)&Cg[(size_t)row * 256 + col] = make_float2(acc[im][jn][0], acc[im][jn][1]);
            *(float2*)&Cg[(size_t)(row + 8) * 256 + col] = make_float2(acc[im][jn][2], acc[im][jn][3]);
        }
    }
}

// ---------------- combine: e = relu(sum partials[pos] + b_soc) scattered to Z (float4) ----------------
__global__ void k_comb(const float* __restrict__ bsoc, const int* __restrict__ Tp, int t)
{
    if (t > *Tp) return;
    int gid = blockIdx.x * 256 + threadIdx.x;   // grid 256 -> 65536 = 1024*64 float4s
    int n = gid >> 6, c4 = (gid & 63) << 2;
    int p = g_posT[t][n];
    float4 s = *(const float4*)&bsoc[c4];
    if (p >= 0) {
        size_t off = (size_t)p * 256 + c4;
        #pragma unroll
        for (int z = 0; z < 4; ++z) {
            float4 e = *(const float4*)&g_E[(size_t)z * (N_AG * 256) + off];
            s.x += e.x; s.y += e.y; s.z += e.z; s.w += e.w;
        }
    }
    s.x = fmaxf(s.x, 0.f); s.y = fmaxf(s.y, 0.f);
    s.z = fmaxf(s.z, 0.f); s.w = fmaxf(s.w, 0.f);
    *(float4*)&g_Z[n * 384 + 64 + c4] = s;
}

// ---------------- per-step: LSTM cell (sums 2 gates partials) + output head ----------------
__global__ void k_lstm(const float* __restrict__ Wout, const float* __restrict__ bout,
                       const int* __restrict__ pm, const float* __restrict__ Y,
                       float* __restrict__ out, const int* __restrict__ Tp, int t)
{
    const int n = blockIdx.x * 8 + (threadIdx.x >> 5);
    const int lane = threadIdx.x & 31;

    if (t > *Tp) {
        if (lane < 2) out[(size_t)(t * N_AG + n) * 2 + lane] = 0.f;
        return;
    }

    const float* g0 = g_E + (size_t)n * 256;
    const float* g1 = g_E + N_AG * 256 + (size_t)n * 256;
    #define GATE(o) (g0[o] + g1[o] + g_bc[o])
    float i0 = GATE(lane),        i1 = GATE(32 + lane);
    float f0 = GATE(64 + lane),   f1 = GATE(96 + lane);
    float gg0 = GATE(128 + lane), gg1 = GATE(160 + lane);
    float o0 = GATE(192 + lane),  o1 = GATE(224 + lane);
    #undef GATE

    float c0 = g_c[n * 64 + lane], c1 = g_c[n * 64 + 32 + lane];
    float cn0 = sigf(f0) * c0 + sigf(i0) * tanhf(gg0);
    float cn1 = sigf(f1) * c1 + sigf(i1) * tanhf(gg1);
    float hn0 = sigf(o0) * tanhf(cn0);
    float hn1 = sigf(o1) * tanhf(cn1);

    g_c[n * 64 + lane] = cn0; g_c[n * 64 + 32 + lane] = cn1;
    g_h[n * 64 + lane] = hn0; g_h[n * 64 + 32 + lane] = hn1;

    float s0 = hn0 * Wout[lane * 2 + 0] + hn1 * Wout[(lane + 32) * 2 + 0];
    float s1 = hn0 * Wout[lane * 2 + 1] + hn1 * Wout[(lane + 32) * 2 + 1];
    #pragma unroll
    for (int off = 16; off; off >>= 1) {
        s0 += __shfl_down_sync(0xFFFFFFFFu, s0, off);
        s1 += __shfl_down_sync(0xFFFFFFFFu, s1, off);
    }

    if (lane == 0) {
        const int m  = pm[t * N_AG + n];
        const int m3 = (t < 3) ? 1 : pm[(t - 3) * N_AG + n];
        float v0 = s0 + bout[0];
        float v1 = s1 + bout[1];
        if (!m) { v0 = 0.f; v1 = 0.f; }
        if (t > 3 && m && !m3) {
            v0 = Y[(size_t)(t * N_AG + n) * 2 + 0];
            v1 = Y[(size_t)(t * N_AG + n) * 2 + 1];
        }
        out[(size_t)(t * N_AG + n) * 2 + 0] = v0;
        out[(size_t)(t * N_AG + n) * 2 + 1] = v1;
    }
}

// ---------------- host launcher (graph-capturable: kernels only) ----------------
extern "C" void kernel_launch(void* const* d_in, const int* in_sizes, int n_in,
                              void* d_out, int out_size)
{
    const float* X    = (const float*)d_in[0];
    const int*   pm   = (const int*)  d_in[1];
    const float* h0   = (const float*)d_in[2];
    const float* c0   = (const float*)d_in[3];
    const float* Y    = (const float*)d_in[4];
    // d_in[5] = T_obs (unused)
    const int*   Tp   = (const int*)  d_in[6];
    const float* Wemb = (const float*)d_in[7];
    const float* bemb = (const float*)d_in[8];
    const float* Wsoc = (const float*)d_in[9];
    const float* bsoc = (const float*)d_in[10];
    const float* Wih  = (const float*)d_in[11];
    const float* bih  = (const float*)d_in[12];
    const float* Whh  = (const float*)d_in[13];
    const float* bhh  = (const float*)d_in[14];
    const float* Wout = (const float*)d_in[15];
    const float* bout = (const float*)d_in[16];
    float* out = (float*)d_out;

    k_init<<<384, 256>>>(h0, c0, Wih, bih, Whh, bhh);
    k_initw<<<KC, 256>>>(Wsoc);
    k_compact_all<<<T_STEPS, 1024>>>(X, pm);    // all per-t tables, once

    for (int t = 0; t < T_STEPS; ++t) {
        k_pool<<<N_AG, 128>>>(X, Wemb, bemb, Tp, t);
        k_mma<0><<<dim3(16, 4, 4), 128>>>(Tp, t);   // social GEMM (compact M), split-K=4
        k_comb<<<256, 256>>>(bsoc, Tp, t);
        k_mma<1><<<dim3(16, 4, 2), 128>>>(Tp, t);   // gates GEMM, split-K=2
        k_lstm<<<128, 256>>>(Wout, bout, pm, Y, out, Tp, t);
    }
}